// round 1
// baseline (speedup 1.0000x reference)
#include <cuda_runtime.h>
#include <math.h>

#define DIM   1024
#define NHEAD 16
#define HDIM  64
#define SEQ   2048
#define BATCH 2
#define MTOT  (BATCH * SEQ)   // 4096

// Scratch (allocation-free rule: __device__ globals)
__device__ float g_qkv[(size_t)BATCH * SEQ * 3 * DIM];  // [b, n, 3*dim]  ~50 MB
__device__ float g_att[(size_t)BATCH * SEQ * DIM];      // [b, n, dim]    ~16 MB

// ---------------------------------------------------------------------------
// SGEMM (NT): C[m][n] = sum_k A[m*K+k] * B[n*K+k] (+ bias[n] if bias != null)
// 128x128 block tile, BK=16, 256 threads, 8x8 microtile.
// ---------------------------------------------------------------------------
__global__ __launch_bounds__(256) void sgemm_nt(
    const float* __restrict__ A, const float* __restrict__ B,
    const float* __restrict__ bias, float* __restrict__ C,
    int M, int N, int K)
{
    constexpr int BK = 16;
    __shared__ float As[BK][132];   // [k][m], padded: conflict-free stores, aligned f4 loads
    __shared__ float Bs[BK][132];   // [k][n]

    const int bm  = blockIdx.y * 128;
    const int bn  = blockIdx.x * 128;
    const int tid = threadIdx.x;
    const int tx  = tid & 15;       // 0..15 -> n microtile
    const int ty  = tid >> 4;       // 0..15 -> m microtile

    // load mapping: 128 rows x 16 k per tile; 8 floats (2 float4) per thread
    const int lrow = tid >> 1;          // 0..127
    const int lk   = (tid & 1) * 8;     // 0 or 8

    const float* Ag = A + (size_t)(bm + lrow) * K + lk;
    const float* Bg = B + (size_t)(bn + lrow) * K + lk;

    float acc[8][8];
#pragma unroll
    for (int i = 0; i < 8; i++)
#pragma unroll
        for (int j = 0; j < 8; j++) acc[i][j] = 0.f;

    for (int k0 = 0; k0 < K; k0 += BK) {
        float4 a0 = *(const float4*)(Ag + k0);
        float4 a1 = *(const float4*)(Ag + k0 + 4);
        float4 b0 = *(const float4*)(Bg + k0);
        float4 b1 = *(const float4*)(Bg + k0 + 4);

        As[lk + 0][lrow] = a0.x; As[lk + 1][lrow] = a0.y;
        As[lk + 2][lrow] = a0.z; As[lk + 3][lrow] = a0.w;
        As[lk + 4][lrow] = a1.x; As[lk + 5][lrow] = a1.y;
        As[lk + 6][lrow] = a1.z; As[lk + 7][lrow] = a1.w;
        Bs[lk + 0][lrow] = b0.x; Bs[lk + 1][lrow] = b0.y;
        Bs[lk + 2][lrow] = b0.z; Bs[lk + 3][lrow] = b0.w;
        Bs[lk + 4][lrow] = b1.x; Bs[lk + 5][lrow] = b1.y;
        Bs[lk + 6][lrow] = b1.z; Bs[lk + 7][lrow] = b1.w;
        __syncthreads();

#pragma unroll
        for (int k = 0; k < BK; k++) {
            float4 x0 = *(const float4*)&As[k][ty * 8];
            float4 x1 = *(const float4*)&As[k][ty * 8 + 4];
            float4 y0 = *(const float4*)&Bs[k][tx * 8];
            float4 y1 = *(const float4*)&Bs[k][tx * 8 + 4];
            float av[8] = {x0.x, x0.y, x0.z, x0.w, x1.x, x1.y, x1.z, x1.w};
            float bv[8] = {y0.x, y0.y, y0.z, y0.w, y1.x, y1.y, y1.z, y1.w};
#pragma unroll
            for (int i = 0; i < 8; i++)
#pragma unroll
                for (int j = 0; j < 8; j++)
                    acc[i][j] += av[i] * bv[j];
        }
        __syncthreads();
    }

#pragma unroll
    for (int i = 0; i < 8; i++) {
        const int row = bm + ty * 8 + i;
        float4 r0 = make_float4(acc[i][0], acc[i][1], acc[i][2], acc[i][3]);
        float4 r1 = make_float4(acc[i][4], acc[i][5], acc[i][6], acc[i][7]);
        if (bias) {
            const float* bp = bias + bn + tx * 8;
            r0.x += bp[0]; r0.y += bp[1]; r0.z += bp[2]; r0.w += bp[3];
            r1.x += bp[4]; r1.y += bp[5]; r1.z += bp[6]; r1.w += bp[7];
        }
        *(float4*)&C[(size_t)row * N + bn + tx * 8]     = r0;
        *(float4*)&C[(size_t)row * N + bn + tx * 8 + 4] = r1;
    }
}

// ---------------------------------------------------------------------------
// Fused flash attention, fp32. grid = (SEQ/64, NHEAD, BATCH), 256 threads.
// qkv layout: [b][n][3*DIM], q at h*64, k at DIM + h*64, v at 2*DIM + h*64.
// Per CTA: 64 q-rows; stream K/V in 64-row tiles with online softmax.
// Smem: Qs + KP + Vs = 3 * 16 KB = 49152 B exactly (static limit).
// ---------------------------------------------------------------------------
__global__ __launch_bounds__(256) void attn_kernel(
    const float* __restrict__ qkv, float* __restrict__ out)
{
    __shared__ float Qs[64][64];   // [d][row]   (transposed)
    __shared__ float KP[64][64];   // K phase: [d][col]; P phase: [row][col]
    __shared__ float Vs[64][64];   // [k][d]

    const int qb = blockIdx.x;
    const int h  = blockIdx.y;
    const int b  = blockIdx.z;
    const int tid = threadIdx.x;
    const int tx  = tid & 15;
    const int ty  = tid >> 4;

    // transpose-load mapping: lane-consecutive rows -> conflict-free stores
    const int r64 = tid & 63;
    const int dq  = (tid >> 6) * 16;

    {   // Q tile: rows qb*64 .. +63, transposed into Qs[d][r]
        const float* qp = qkv + ((size_t)(b * SEQ + qb * 64 + r64)) * (3 * DIM) + h * HDIM + dq;
        float4 v0 = *(const float4*)(qp);
        float4 v1 = *(const float4*)(qp + 4);
        float4 v2 = *(const float4*)(qp + 8);
        float4 v3 = *(const float4*)(qp + 12);
        Qs[dq + 0][r64] = v0.x; Qs[dq + 1][r64] = v0.y; Qs[dq + 2][r64] = v0.z; Qs[dq + 3][r64] = v0.w;
        Qs[dq + 4][r64] = v1.x; Qs[dq + 5][r64] = v1.y; Qs[dq + 6][r64] = v1.z; Qs[dq + 7][r64] = v1.w;
        Qs[dq + 8][r64] = v2.x; Qs[dq + 9][r64] = v2.y; Qs[dq +10][r64] = v2.z; Qs[dq +11][r64] = v2.w;
        Qs[dq +12][r64] = v3.x; Qs[dq +13][r64] = v3.y; Qs[dq +14][r64] = v3.z; Qs[dq +15][r64] = v3.w;
    }

    float o[4][4];
    float mi[4], li[4];
#pragma unroll
    for (int i = 0; i < 4; i++) {
        mi[i] = -1e30f; li[i] = 0.f;
#pragma unroll
        for (int j = 0; j < 4; j++) o[i][j] = 0.f;
    }

    const float scale = 0.03125f;  // 1024^-0.5 exactly

    for (int kt = 0; kt < SEQ; kt += 64) {
        __syncthreads();  // previous PV reads of KP/Vs done

        {   // K tile transposed into KP[d][c]
            const float* kp = qkv + ((size_t)(b * SEQ + kt + r64)) * (3 * DIM) + DIM + h * HDIM + dq;
            float4 v0 = *(const float4*)(kp);
            float4 v1 = *(const float4*)(kp + 4);
            float4 v2 = *(const float4*)(kp + 8);
            float4 v3 = *(const float4*)(kp + 12);
            KP[dq + 0][r64] = v0.x; KP[dq + 1][r64] = v0.y; KP[dq + 2][r64] = v0.z; KP[dq + 3][r64] = v0.w;
            KP[dq + 4][r64] = v1.x; KP[dq + 5][r64] = v1.y; KP[dq + 6][r64] = v1.z; KP[dq + 7][r64] = v1.w;
            KP[dq + 8][r64] = v2.x; KP[dq + 9][r64] = v2.y; KP[dq +10][r64] = v2.z; KP[dq +11][r64] = v2.w;
            KP[dq +12][r64] = v3.x; KP[dq +13][r64] = v3.y; KP[dq +14][r64] = v3.z; KP[dq +15][r64] = v3.w;
        }
        {   // V tile straight copy into Vs[k][d]
#pragma unroll
            for (int s = 0; s < 4; s++) {
                int f   = tid + s * 256;
                int row = f >> 4;
                int c4  = (f & 15) * 4;
                const float* vp = qkv + ((size_t)(b * SEQ + kt + row)) * (3 * DIM) + 2 * DIM + h * HDIM + c4;
                *(float4*)&Vs[row][c4] = *(const float4*)vp;
            }
        }
        __syncthreads();

        // S = scale * Q K^T  (4x4 per thread: rows 4ty+i, cols 4tx+j)
        float s[4][4];
#pragma unroll
        for (int i = 0; i < 4; i++)
#pragma unroll
            for (int j = 0; j < 4; j++) s[i][j] = 0.f;

#pragma unroll 8
        for (int d = 0; d < 64; d++) {
            float4 av = *(const float4*)&Qs[d][ty * 4];
            float4 bv = *(const float4*)&KP[d][tx * 4];
            s[0][0] += av.x * bv.x; s[0][1] += av.x * bv.y; s[0][2] += av.x * bv.z; s[0][3] += av.x * bv.w;
            s[1][0] += av.y * bv.x; s[1][1] += av.y * bv.y; s[1][2] += av.y * bv.z; s[1][3] += av.y * bv.w;
            s[2][0] += av.z * bv.x; s[2][1] += av.z * bv.y; s[2][2] += av.z * bv.z; s[2][3] += av.z * bv.w;
            s[3][0] += av.w * bv.x; s[3][1] += av.w * bv.y; s[3][2] += av.w * bv.z; s[3][3] += av.w * bv.w;
        }

        // online softmax (row groups = 16 contiguous lanes within warp)
        float rmax[4], rsum[4], corr[4], p[4][4];
#pragma unroll
        for (int i = 0; i < 4; i++) {
#pragma unroll
            for (int j = 0; j < 4; j++) s[i][j] *= scale;
            rmax[i] = fmaxf(fmaxf(s[i][0], s[i][1]), fmaxf(s[i][2], s[i][3]));
        }
#pragma unroll
        for (int off = 8; off >= 1; off >>= 1)
#pragma unroll
            for (int i = 0; i < 4; i++)
                rmax[i] = fmaxf(rmax[i], __shfl_xor_sync(0xffffffffu, rmax[i], off));

#pragma unroll
        for (int i = 0; i < 4; i++) {
            float mnew = fmaxf(mi[i], rmax[i]);
            corr[i] = __expf(mi[i] - mnew);
            mi[i] = mnew;
            rsum[i] = 0.f;
#pragma unroll
            for (int j = 0; j < 4; j++) {
                p[i][j] = __expf(s[i][j] - mnew);
                rsum[i] += p[i][j];
            }
        }
#pragma unroll
        for (int off = 8; off >= 1; off >>= 1)
#pragma unroll
            for (int i = 0; i < 4; i++)
                rsum[i] += __shfl_xor_sync(0xffffffffu, rsum[i], off);

#pragma unroll
        for (int i = 0; i < 4; i++) {
            li[i] = li[i] * corr[i] + rsum[i];
#pragma unroll
            for (int j = 0; j < 4; j++) o[i][j] *= corr[i];
        }

        __syncthreads();  // everyone finished reading KP as K
        // P into KP buffer, row-major [row][col], float4 stores
#pragma unroll
        for (int i = 0; i < 4; i++)
            *(float4*)&KP[ty * 4 + i][tx * 4] = make_float4(p[i][0], p[i][1], p[i][2], p[i][3]);
        __syncthreads();

        // O += P @ V  (rows 4ty+i, d-cols 4tx+j)
#pragma unroll 2
        for (int k = 0; k < 64; k += 4) {
            float4 a0 = *(const float4*)&KP[ty * 4 + 0][k];
            float4 a1 = *(const float4*)&KP[ty * 4 + 1][k];
            float4 a2 = *(const float4*)&KP[ty * 4 + 2][k];
            float4 a3 = *(const float4*)&KP[ty * 4 + 3][k];
            float4 v0 = *(const float4*)&Vs[k + 0][tx * 4];
            float4 v1 = *(const float4*)&Vs[k + 1][tx * 4];
            float4 v2 = *(const float4*)&Vs[k + 2][tx * 4];
            float4 v3 = *(const float4*)&Vs[k + 3][tx * 4];
            o[0][0] += a0.x*v0.x + a0.y*v1.x + a0.z*v2.x + a0.w*v3.x;
            o[0][1] += a0.x*v0.y + a0.y*v1.y + a0.z*v2.y + a0.w*v3.y;
            o[0][2] += a0.x*v0.z + a0.y*v1.z + a0.z*v2.z + a0.w*v3.z;
            o[0][3] += a0.x*v0.w + a0.y*v1.w + a0.z*v2.w + a0.w*v3.w;
            o[1][0] += a1.x*v0.x + a1.y*v1.x + a1.z*v2.x + a1.w*v3.x;
            o[1][1] += a1.x*v0.y + a1.y*v1.y + a1.z*v2.y + a1.w*v3.y;
            o[1][2] += a1.x*v0.z + a1.y*v1.z + a1.z*v2.z + a1.w*v3.z;
            o[1][3] += a1.x*v0.w + a1.y*v1.w + a1.z*v2.w + a1.w*v3.w;
            o[2][0] += a2.x*v0.x + a2.y*v1.x + a2.z*v2.x + a2.w*v3.x;
            o[2][1] += a2.x*v0.y + a2.y*v1.y + a2.z*v2.y + a2.w*v3.y;
            o[2][2] += a2.x*v0.z + a2.y*v1.z + a2.z*v2.z + a2.w*v3.z;
            o[2][3] += a2.x*v0.w + a2.y*v1.w + a2.z*v2.w + a2.w*v3.w;
            o[3][0] += a3.x*v0.x + a3.y*v1.x + a3.z*v2.x + a3.w*v3.x;
            o[3][1] += a3.x*v0.y + a3.y*v1.y + a3.z*v2.y + a3.w*v3.y;
            o[3][2] += a3.x*v0.z + a3.y*v1.z + a3.z*v2.z + a3.w*v3.z;
            o[3][3] += a3.x*v0.w + a3.y*v1.w + a3.z*v2.w + a3.w*v3.w;
        }
    }

    // write O/l  -> g_att[b][n][h*64 + d]  (heads re-interleaved)
#pragma unroll
    for (int i = 0; i < 4; i++) {
        float inv = 1.f / li[i];
        float4 r = make_float4(o[i][0] * inv, o[i][1] * inv, o[i][2] * inv, o[i][3] * inv);
        *(float4*)&out[((size_t)(b * SEQ + qb * 64 + ty * 4 + i)) * DIM + h * HDIM + tx * 4] = r;
    }
}

// ---------------------------------------------------------------------------
extern "C" void kernel_launch(void* const* d_in, const int* in_sizes, int n_in,
                              void* d_out, int out_size)
{
    const float* x     = (const float*)d_in[0];
    const float* w_qkv = (const float*)d_in[1];
    const float* w_o   = (const float*)d_in[2];
    const float* b_o   = (const float*)d_in[3];
    float* out = (float*)d_out;

    float* qkv = nullptr;
    float* att = nullptr;
    cudaGetSymbolAddress((void**)&qkv, g_qkv);
    cudaGetSymbolAddress((void**)&att, g_att);

    // 1) QKV projection: [4096,1024] @ [3072,1024]^T -> [4096,3072]
    sgemm_nt<<<dim3(3 * DIM / 128, MTOT / 128), 256>>>(x, w_qkv, nullptr, qkv,
                                                       MTOT, 3 * DIM, DIM);
    // 2) fused attention -> [4096,1024] (heads merged)
    attn_kernel<<<dim3(SEQ / 64, NHEAD, BATCH), 256>>>(qkv, att);
    // 3) output projection + bias: [4096,1024] @ [1024,1024]^T + b
    sgemm_nt<<<dim3(DIM / 128, MTOT / 128), 256>>>(att, w_o, b_o, out,
                                                   MTOT, DIM, DIM);
}

// round 2
// speedup vs baseline: 3.1820x; 3.1820x over previous
#include <cuda_runtime.h>
#include <math.h>

#define DIM   1024
#define NHEAD 16
#define HDIM  64
#define SEQ   2048
#define BATCH 2
#define MTOT  (BATCH * SEQ)   // 4096

// Scratch (allocation-free rule: __device__ globals)
__device__ float g_qkv[(size_t)BATCH * SEQ * 3 * DIM];  // [b, n, 3*dim]
__device__ float g_att[(size_t)BATCH * SEQ * DIM];      // [b, n, dim]

// ---------------------------------------------------------------------------
// helpers
// ---------------------------------------------------------------------------
__device__ __forceinline__ float to_tf32(float x) {
    float y;
    asm("cvt.rna.tf32.f32 %0, %1;" : "=f"(y) : "f"(x));
    return y;
}

__device__ __forceinline__ void mma_tf32(float d[4],
                                         unsigned a0, unsigned a1, unsigned a2, unsigned a3,
                                         unsigned b0, unsigned b1)
{
    asm volatile(
        "mma.sync.aligned.m16n8k8.row.col.f32.tf32.tf32.f32 "
        "{%0,%1,%2,%3}, {%4,%5,%6,%7}, {%8,%9}, {%0,%1,%2,%3};\n"
        : "+f"(d[0]), "+f"(d[1]), "+f"(d[2]), "+f"(d[3])
        : "r"(a0), "r"(a1), "r"(a2), "r"(a3), "r"(b0), "r"(b1));
}

// FFMA-only exp: avoids MUFU (rt=8/SMSP) which was the attention bottleneck.
// Valid for x <= 0 (softmax args are always <= 0). ~1e-7 rel accuracy.
__device__ __forceinline__ float fast_exp(float x) {
    float t = fmaxf(x * 1.4426950408889634f, -126.0f);   // log2(e), clamp
    float z = t + 12582912.0f;                            // 1.5 * 2^23 round trick
    int   n = __float_as_int(z) - 0x4B400000;             // n = round(t)
    float f = t - (z - 12582912.0f);                      // f in [-0.5, 0.5]
    float r = 1.3333558146e-3f;                           // ln2^5/120
    r = fmaf(r, f, 9.6181291076e-3f);                     // ln2^4/24
    r = fmaf(r, f, 5.5504108664e-2f);                     // ln2^3/6
    r = fmaf(r, f, 2.4022650696e-1f);                     // ln2^2/2
    r = fmaf(r, f, 6.9314718056e-1f);                     // ln2
    r = fmaf(r, f, 1.0f);
    return r * __int_as_float((n + 127) << 23);           // * 2^n
}

// ---------------------------------------------------------------------------
// tf32 tensor-core GEMM (NT): C[m][n] = sum_k A[m][k]*B[n][k] (+bias[n])
// CTA 128x128, BK=32, 256 threads (8 warps, 2x4), warp tile 64x32 via
// m16n8k8 tf32 mma. Smem strides padded so all fragment loads are
// bank-conflict-free (bank = 4*row + k, distinct over a frag's footprint).
// ---------------------------------------------------------------------------
__global__ __launch_bounds__(256) void gemm_tf32(
    const float* __restrict__ A, const float* __restrict__ B,
    const float* __restrict__ bias, float* __restrict__ C,
    int M, int N, int K)
{
    __shared__ float As[128][36];   // [m][k]
    __shared__ float Bs[128][36];   // [n][k]

    const int tid  = threadIdx.x;
    const int lane = tid & 31;
    const int wid  = tid >> 5;
    const int wm   = (wid & 1) * 64;   // warp m-offset in CTA tile
    const int wn   = (wid >> 1) * 32;  // warp n-offset
    const int g    = lane >> 2;        // group id (row within frag)
    const int tg   = lane & 3;         // thread-in-group (k within frag)

    const int bm = blockIdx.y * 128;
    const int bn = blockIdx.x * 128;

    float acc[4][4][4];
#pragma unroll
    for (int mt = 0; mt < 4; mt++)
#pragma unroll
        for (int nt = 0; nt < 4; nt++)
#pragma unroll
            for (int r = 0; r < 4; r++) acc[mt][nt][r] = 0.f;

    for (int k0 = 0; k0 < K; k0 += 32) {
#pragma unroll
        for (int i = 0; i < 4; i++) {
            const int idx = tid + i * 256;
            const int row = idx >> 3;
            const int kq  = (idx & 7) << 2;
            float4 a = *(const float4*)&A[(size_t)(bm + row) * K + k0 + kq];
            float4 b = *(const float4*)&B[(size_t)(bn + row) * K + k0 + kq];
            *(float4*)&As[row][kq] = make_float4(to_tf32(a.x), to_tf32(a.y),
                                                 to_tf32(a.z), to_tf32(a.w));
            *(float4*)&Bs[row][kq] = make_float4(to_tf32(b.x), to_tf32(b.y),
                                                 to_tf32(b.z), to_tf32(b.w));
        }
        __syncthreads();

#pragma unroll
        for (int kk = 0; kk < 32; kk += 8) {
            unsigned ar[4][4], br[4][2];
#pragma unroll
            for (int mt = 0; mt < 4; mt++) {
                const int r = wm + mt * 16 + g;
                ar[mt][0] = __float_as_uint(As[r    ][kk + tg    ]);
                ar[mt][1] = __float_as_uint(As[r + 8][kk + tg    ]);
                ar[mt][2] = __float_as_uint(As[r    ][kk + tg + 4]);
                ar[mt][3] = __float_as_uint(As[r + 8][kk + tg + 4]);
            }
#pragma unroll
            for (int nt = 0; nt < 4; nt++) {
                const int c = wn + nt * 8 + g;
                br[nt][0] = __float_as_uint(Bs[c][kk + tg    ]);
                br[nt][1] = __float_as_uint(Bs[c][kk + tg + 4]);
            }
#pragma unroll
            for (int mt = 0; mt < 4; mt++)
#pragma unroll
                for (int nt = 0; nt < 4; nt++)
                    mma_tf32(acc[mt][nt], ar[mt][0], ar[mt][1], ar[mt][2], ar[mt][3],
                             br[nt][0], br[nt][1]);
        }
        __syncthreads();
    }

#pragma unroll
    for (int mt = 0; mt < 4; mt++) {
        const int row0 = bm + wm + mt * 16 + g;
#pragma unroll
        for (int nt = 0; nt < 4; nt++) {
            const int col = bn + wn + nt * 8 + 2 * tg;
            float b0 = 0.f, b1 = 0.f;
            if (bias) { b0 = bias[col]; b1 = bias[col + 1]; }
            *(float2*)&C[(size_t)row0 * N + col] =
                make_float2(acc[mt][nt][0] + b0, acc[mt][nt][1] + b1);
            *(float2*)&C[(size_t)(row0 + 8) * N + col] =
                make_float2(acc[mt][nt][2] + b0, acc[mt][nt][3] + b1);
        }
    }
}

// ---------------------------------------------------------------------------
// Fused flash attention, tf32 tensor cores + FFMA softmax.
// grid = (SEQ/64, NHEAD, BATCH), 128 threads (4 warps). Each warp owns 16
// q-rows; key tiles of 64 streamed with online softmax.
// Smem (dynamic 53248B): Qs[64][68], KP[64][68] (K, then reused for P),
// Vs[64][72]. Strides chosen conflict-free for the mma fragment patterns.
// ---------------------------------------------------------------------------
#define QS(r, c) Qs[(r) * 68 + (c)]
#define KPS(r, c) KP[(r) * 68 + (c)]
#define VSS(r, c) Vs[(r) * 72 + (c)]

__global__ __launch_bounds__(128) void attn_tf32(
    const float* __restrict__ qkv, float* __restrict__ out)
{
    extern __shared__ float smem[];
    float* Qs = smem;
    float* KP = smem + 64 * 68;
    float* Vs = smem + 2 * 64 * 68;

    const int qb = blockIdx.x;
    const int h  = blockIdx.y;
    const int b  = blockIdx.z;
    const int tid  = threadIdx.x;
    const int lane = tid & 31;
    const int wid  = tid >> 5;
    const int g    = lane >> 2;
    const int tg   = lane & 3;
    const int wq   = wid * 16;      // warp's q-row offset within the 64-row tile

    // load Q tile (64 x 64), tf32-converted
#pragma unroll
    for (int i = 0; i < 8; i++) {
        const int idx = tid + i * 128;
        const int row = idx >> 4;
        const int c4  = (idx & 15) << 2;
        float4 v = *(const float4*)&qkv[((size_t)(b * SEQ + qb * 64 + row)) * (3 * DIM)
                                        + h * HDIM + c4];
        *(float4*)&QS(row, c4) = make_float4(to_tf32(v.x), to_tf32(v.y),
                                             to_tf32(v.z), to_tf32(v.w));
    }

    float of[8][4];
    float mi0 = -1e30f, mi1 = -1e30f, li0 = 0.f, li1 = 0.f;
#pragma unroll
    for (int nt = 0; nt < 8; nt++)
#pragma unroll
        for (int r = 0; r < 4; r++) of[nt][r] = 0.f;

    const float scale = 0.03125f;   // 1024^-0.5

    for (int kt = 0; kt < SEQ; kt += 64) {
        __syncthreads();   // prior PV reads of KP/Vs (and Q stores on iter 0) done

        // load K, V tiles (tf32)
#pragma unroll
        for (int i = 0; i < 8; i++) {
            const int idx = tid + i * 128;
            const int row = idx >> 4;
            const int c4  = (idx & 15) << 2;
            const size_t base = ((size_t)(b * SEQ + kt + row)) * (3 * DIM) + h * HDIM;
            float4 kv = *(const float4*)&qkv[base + DIM + c4];
            float4 vv = *(const float4*)&qkv[base + 2 * DIM + c4];
            *(float4*)&KPS(row, c4) = make_float4(to_tf32(kv.x), to_tf32(kv.y),
                                                  to_tf32(kv.z), to_tf32(kv.w));
            *(float4*)&VSS(row, c4) = make_float4(to_tf32(vv.x), to_tf32(vv.y),
                                                  to_tf32(vv.z), to_tf32(vv.w));
        }
        __syncthreads();

        // S = Q K^T  (warp: 16 q-rows x 64 keys, 8 n-tiles)
        float sf[8][4];
#pragma unroll
        for (int nt = 0; nt < 8; nt++)
#pragma unroll
            for (int r = 0; r < 4; r++) sf[nt][r] = 0.f;

#pragma unroll
        for (int kk = 0; kk < 64; kk += 8) {
            unsigned a0 = __float_as_uint(QS(wq + g,     kk + tg));
            unsigned a1 = __float_as_uint(QS(wq + g + 8, kk + tg));
            unsigned a2 = __float_as_uint(QS(wq + g,     kk + tg + 4));
            unsigned a3 = __float_as_uint(QS(wq + g + 8, kk + tg + 4));
#pragma unroll
            for (int nt = 0; nt < 8; nt++) {
                unsigned b0 = __float_as_uint(KPS(nt * 8 + g, kk + tg));
                unsigned b1 = __float_as_uint(KPS(nt * 8 + g, kk + tg + 4));
                mma_tf32(sf[nt], a0, a1, a2, a3, b0, b1);
            }
        }

        // online softmax. row0 = wq+g (regs 0,1), row1 = wq+g+8 (regs 2,3).
        float m0 = -1e30f, m1 = -1e30f;
#pragma unroll
        for (int nt = 0; nt < 8; nt++) {
            sf[nt][0] *= scale; sf[nt][1] *= scale;
            sf[nt][2] *= scale; sf[nt][3] *= scale;
            m0 = fmaxf(m0, fmaxf(sf[nt][0], sf[nt][1]));
            m1 = fmaxf(m1, fmaxf(sf[nt][2], sf[nt][3]));
        }
        m0 = fmaxf(m0, __shfl_xor_sync(0xffffffffu, m0, 1));
        m0 = fmaxf(m0, __shfl_xor_sync(0xffffffffu, m0, 2));
        m1 = fmaxf(m1, __shfl_xor_sync(0xffffffffu, m1, 1));
        m1 = fmaxf(m1, __shfl_xor_sync(0xffffffffu, m1, 2));

        const float mn0 = fmaxf(mi0, m0);
        const float mn1 = fmaxf(mi1, m1);
        const float corr0 = fast_exp(mi0 - mn0);
        const float corr1 = fast_exp(mi1 - mn1);
        mi0 = mn0; mi1 = mn1;

        float s0 = 0.f, s1 = 0.f;
#pragma unroll
        for (int nt = 0; nt < 8; nt++) {
            sf[nt][0] = fast_exp(sf[nt][0] - mn0);
            sf[nt][1] = fast_exp(sf[nt][1] - mn0);
            sf[nt][2] = fast_exp(sf[nt][2] - mn1);
            sf[nt][3] = fast_exp(sf[nt][3] - mn1);
            s0 += sf[nt][0] + sf[nt][1];
            s1 += sf[nt][2] + sf[nt][3];
        }
        s0 += __shfl_xor_sync(0xffffffffu, s0, 1);
        s0 += __shfl_xor_sync(0xffffffffu, s0, 2);
        s1 += __shfl_xor_sync(0xffffffffu, s1, 1);
        s1 += __shfl_xor_sync(0xffffffffu, s1, 2);

        li0 = li0 * corr0 + s0;
        li1 = li1 * corr1 + s1;
#pragma unroll
        for (int nt = 0; nt < 8; nt++) {
            of[nt][0] *= corr0; of[nt][1] *= corr0;
            of[nt][2] *= corr1; of[nt][3] *= corr1;
        }

        __syncthreads();   // everyone done reading KP as K
        // P -> KP buffer (tf32), row-major [qrow][key]
#pragma unroll
        for (int nt = 0; nt < 8; nt++) {
            *(float2*)&KPS(wq + g, nt * 8 + 2 * tg) =
                make_float2(to_tf32(sf[nt][0]), to_tf32(sf[nt][1]));
            *(float2*)&KPS(wq + g + 8, nt * 8 + 2 * tg) =
                make_float2(to_tf32(sf[nt][2]), to_tf32(sf[nt][3]));
        }
        __syncthreads();

        // O += P @ V   (k = key dim 64, n-tiles over d)
#pragma unroll
        for (int kk = 0; kk < 64; kk += 8) {
            unsigned a0 = __float_as_uint(KPS(wq + g,     kk + tg));
            unsigned a1 = __float_as_uint(KPS(wq + g + 8, kk + tg));
            unsigned a2 = __float_as_uint(KPS(wq + g,     kk + tg + 4));
            unsigned a3 = __float_as_uint(KPS(wq + g + 8, kk + tg + 4));
#pragma unroll
            for (int nt = 0; nt < 8; nt++) {
                unsigned b0 = __float_as_uint(VSS(kk + tg,     nt * 8 + g));
                unsigned b1 = __float_as_uint(VSS(kk + tg + 4, nt * 8 + g));
                mma_tf32(of[nt], a0, a1, a2, a3, b0, b1);
            }
        }
    }

    // normalize and write (heads re-interleaved into [b][n][h*64+d])
    const float inv0 = 1.f / li0;
    const float inv1 = 1.f / li1;
    const size_t row0 = (size_t)(b * SEQ + qb * 64 + wq + g);
#pragma unroll
    for (int nt = 0; nt < 8; nt++) {
        const int col = h * HDIM + nt * 8 + 2 * tg;
        *(float2*)&out[row0 * DIM + col] =
            make_float2(of[nt][0] * inv0, of[nt][1] * inv0);
        *(float2*)&out[(row0 + 8) * DIM + col] =
            make_float2(of[nt][2] * inv1, of[nt][3] * inv1);
    }
}

// ---------------------------------------------------------------------------
extern "C" void kernel_launch(void* const* d_in, const int* in_sizes, int n_in,
                              void* d_out, int out_size)
{
    const float* x     = (const float*)d_in[0];
    const float* w_qkv = (const float*)d_in[1];
    const float* w_o   = (const float*)d_in[2];
    const float* b_o   = (const float*)d_in[3];
    float* out = (float*)d_out;

    float* qkv = nullptr;
    float* att = nullptr;
    cudaGetSymbolAddress((void**)&qkv, g_qkv);
    cudaGetSymbolAddress((void**)&att, g_att);

    const int attn_smem = (2 * 64 * 68 + 64 * 72) * 4;   // 53248 B
    cudaFuncSetAttribute(attn_tf32, cudaFuncAttributeMaxDynamicSharedMemorySize,
                         attn_smem);

    // 1) QKV projection: [4096,1024] @ [3072,1024]^T -> [4096,3072]
    gemm_tf32<<<dim3(3 * DIM / 128, MTOT / 128), 256>>>(x, w_qkv, nullptr, qkv,
                                                        MTOT, 3 * DIM, DIM);
    // 2) fused attention -> [4096,1024]
    attn_tf32<<<dim3(SEQ / 64, NHEAD, BATCH), 128, attn_smem>>>(qkv, att);
    // 3) output projection + bias
    gemm_tf32<<<dim3(DIM / 128, MTOT / 128), 256>>>(att, w_o, b_o, out,
                                                    MTOT, DIM, DIM);
}

// round 4
// speedup vs baseline: 3.5771x; 1.1242x over previous
#include <cuda_runtime.h>
#include <cstdint>
#include <math.h>

#define DIM   1024
#define NHEAD 16
#define HDIM  64
#define SEQ   2048
#define BATCH 2
#define MTOT  (BATCH * SEQ)   // 4096

// Scratch (allocation-free rule: __device__ globals)
__device__ float g_qkv[(size_t)BATCH * SEQ * 3 * DIM];   // qkv proj out (tf32-rounded)
__device__ float g_att[(size_t)BATCH * SEQ * DIM];       // attn out (tf32-rounded)
__device__ float g_xc[(size_t)MTOT * DIM];               // x, tf32-rounded
__device__ float g_wqkvc[(size_t)3 * DIM * DIM];         // w_qkv, tf32-rounded
__device__ float g_woc[(size_t)DIM * DIM];               // w_o, tf32-rounded

// ---------------------------------------------------------------------------
// helpers
// ---------------------------------------------------------------------------
__device__ __forceinline__ uint32_t smem_u32(const void* p) {
    uint32_t a;
    asm("{ .reg .u64 t; cvta.to.shared.u64 t, %1; cvt.u32.u64 %0, t; }"
        : "=r"(a) : "l"(p));
    return a;
}
__device__ __forceinline__ float to_tf32(float x) {
    float y;
    asm("cvt.rna.tf32.f32 %0, %1;" : "=f"(y) : "f"(x));
    return y;
}
__device__ __forceinline__ void mma_tf32(float d[4],
                                         unsigned a0, unsigned a1, unsigned a2, unsigned a3,
                                         unsigned b0, unsigned b1) {
    asm volatile(
        "mma.sync.aligned.m16n8k8.row.col.f32.tf32.tf32.f32 "
        "{%0,%1,%2,%3}, {%4,%5,%6,%7}, {%8,%9}, {%0,%1,%2,%3};\n"
        : "+f"(d[0]), "+f"(d[1]), "+f"(d[2]), "+f"(d[3])
        : "r"(a0), "r"(a1), "r"(a2), "r"(a3), "r"(b0), "r"(b1));
}
#define CP_ASYNC16(dst, src) \
    asm volatile("cp.async.cg.shared.global [%0], [%1], 16;" :: "r"(dst), "l"(src))
#define CP_COMMIT() asm volatile("cp.async.commit_group;" ::: "memory")
#define CP_WAIT1()  asm volatile("cp.async.wait_group 1;" ::: "memory")

// FFMA-only exp (valid for x <= 0); avoids the MUFU throughput wall.
__device__ __forceinline__ float fast_exp(float x) {
    float t = fmaxf(x * 1.4426950408889634f, -126.0f);
    float z = t + 12582912.0f;
    int   n = __float_as_int(z) - 0x4B400000;
    float f = t - (z - 12582912.0f);
    float r = 1.3333558146e-3f;
    r = fmaf(r, f, 9.6181291076e-3f);
    r = fmaf(r, f, 5.5504108664e-2f);
    r = fmaf(r, f, 2.4022650696e-1f);
    r = fmaf(r, f, 6.9314718056e-1f);
    r = fmaf(r, f, 1.0f);
    return r * __int_as_float((n + 127) << 23);
}

// ---------------------------------------------------------------------------
// pre-pass: round fp32 -> tf32-in-fp32 (so GEMMs can ingest raw, cvt-free)
// ---------------------------------------------------------------------------
__global__ __launch_bounds__(256) void round_tf32(const float* __restrict__ in,
                                                  float* __restrict__ out, int n4)
{
    int i = blockIdx.x * blockDim.x + threadIdx.x;
    if (i < n4) {
        float4 v = ((const float4*)in)[i];
        ((float4*)out)[i] = make_float4(to_tf32(v.x), to_tf32(v.y),
                                        to_tf32(v.z), to_tf32(v.w));
    }
}

// ---------------------------------------------------------------------------
// tf32 mma.sync GEMM (NT) with cp.async 3-stage pipeline.
// C[m][n] = sum_k A[m][k]*B[n][k] (+bias). A,B must be tf32-pre-rounded.
// CTA 128x128, BK=32 (one 128B row per tile row), 256 threads, warp 64x32.
// Smem: 3 stages x (16KB A + 16KB B) = 96KB. XOR-swizzle (16B grp ^ row&7)
// makes LDGSTS stores and all fragment LDS bank-conflict-free.
// ---------------------------------------------------------------------------
#define GSTAGE_F 8192            // floats per stage (A 4096 + B 4096)
#define G_SMEM   (3 * GSTAGE_F * 4)   // 98304 B

__global__ __launch_bounds__(256) void gemm_cp(
    const float* __restrict__ A, const float* __restrict__ B,
    const float* __restrict__ bias, float* __restrict__ C,
    int N, int round_out)
{
    extern __shared__ float sm[];
    const uint32_t sb = smem_u32(sm);

    const int tid  = threadIdx.x;
    const int lane = tid & 31;
    const int wid  = tid >> 5;
    const int wm   = (wid & 1) * 64;
    const int wn   = (wid >> 1) * 32;
    const int g    = lane >> 2;
    const int tg   = lane & 3;
    const int bm   = blockIdx.y * 128;
    const int bn   = blockIdx.x * 128;

    // cp.async thread mapping: 4 A-chunks + 4 B-chunks of 16B per thread
    const int lrow = tid >> 3;        // 0..31 (x4 via j)
    const int lgrp = tid & 7;         // 16B group within 128B row

    float acc[4][4][4];
#pragma unroll
    for (int mt = 0; mt < 4; mt++)
#pragma unroll
        for (int nt = 0; nt < 4; nt++)
#pragma unroll
            for (int r = 0; r < 4; r++) acc[mt][nt][r] = 0.f;

    // ---- pipeline prologue: stages 0,1 ----
#pragma unroll
    for (int c = 0; c < 2; c++) {
        const uint32_t st = sb + c * (GSTAGE_F * 4);
        const int k0 = c * 32;
#pragma unroll
        for (int j = 0; j < 4; j++) {
            const int row = lrow + j * 32;
            const uint32_t off = row * 128 + ((lgrp ^ (row & 7)) << 4);
            CP_ASYNC16(st + off,          &A[(size_t)(bm + row) * 1024 + k0 + lgrp * 4]);
            CP_ASYNC16(st + 16384 + off,  &B[(size_t)(bn + row) * 1024 + k0 + lgrp * 4]);
        }
        CP_COMMIT();
    }

    for (int c = 0; c < 32; c++) {
        CP_WAIT1();
        __syncthreads();

        const int s = c - (c / 3) * 3;          // c % 3
        const float* As = sm + s * GSTAGE_F;
        const float* Bs = As + 4096;

#pragma unroll
        for (int kk = 0; kk < 32; kk += 8) {
            const int ga  = (((kk >> 2)    ) ^ g) << 2;   // swizzled grp, k=kk+tg
            const int ga4 = (((kk >> 2) + 1) ^ g) << 2;   // k=kk+tg+4
            unsigned ar[4][4], br[4][2];
#pragma unroll
            for (int mt = 0; mt < 4; mt++) {
                const int r0 = (wm + mt * 16 + g) * 32;
                const int r1 = r0 + 8 * 32;
                ar[mt][0] = __float_as_uint(As[r0 + ga  + tg]);
                ar[mt][1] = __float_as_uint(As[r1 + ga  + tg]);
                ar[mt][2] = __float_as_uint(As[r0 + ga4 + tg]);
                ar[mt][3] = __float_as_uint(As[r1 + ga4 + tg]);
            }
#pragma unroll
            for (int nt = 0; nt < 4; nt++) {
                const int r = (wn + nt * 8 + g) * 32;
                br[nt][0] = __float_as_uint(Bs[r + ga  + tg]);
                br[nt][1] = __float_as_uint(Bs[r + ga4 + tg]);
            }
#pragma unroll
            for (int mt = 0; mt < 4; mt++)
#pragma unroll
                for (int nt = 0; nt < 4; nt++)
                    mma_tf32(acc[mt][nt], ar[mt][0], ar[mt][1], ar[mt][2], ar[mt][3],
                             br[nt][0], br[nt][1]);
        }

        if (c + 2 < 32) {
            const int s2 = (c + 2) - ((c + 2) / 3) * 3;
            const uint32_t st = sb + s2 * (GSTAGE_F * 4);
            const int k0 = (c + 2) * 32;
#pragma unroll
            for (int j = 0; j < 4; j++) {
                const int row = lrow + j * 32;
                const uint32_t off = row * 128 + ((lgrp ^ (row & 7)) << 4);
                CP_ASYNC16(st + off,         &A[(size_t)(bm + row) * 1024 + k0 + lgrp * 4]);
                CP_ASYNC16(st + 16384 + off, &B[(size_t)(bn + row) * 1024 + k0 + lgrp * 4]);
            }
        }
        CP_COMMIT();
    }

    // ---- epilogue ----
#pragma unroll
    for (int mt = 0; mt < 4; mt++) {
        const int row0 = bm + wm + mt * 16 + g;
#pragma unroll
        for (int nt = 0; nt < 4; nt++) {
            const int col = bn + wn + nt * 8 + 2 * tg;
            float b0 = 0.f, b1 = 0.f;
            if (bias) { b0 = bias[col]; b1 = bias[col + 1]; }
            float v00 = acc[mt][nt][0] + b0, v01 = acc[mt][nt][1] + b1;
            float v10 = acc[mt][nt][2] + b0, v11 = acc[mt][nt][3] + b1;
            if (round_out) {
                v00 = to_tf32(v00); v01 = to_tf32(v01);
                v10 = to_tf32(v10); v11 = to_tf32(v11);
            }
            *(float2*)&C[(size_t)row0 * N + col]       = make_float2(v00, v01);
            *(float2*)&C[(size_t)(row0 + 8) * N + col] = make_float2(v10, v11);
        }
    }
}

// ---------------------------------------------------------------------------
// Fused flash attention (round-2 structure; qkv is pre-rounded so no cvt on
// load; output written tf32-rounded for the cvt-free out-projection).
// ---------------------------------------------------------------------------
#define QS(r, c) Qs[(r) * 68 + (c)]
#define KPS(r, c) KP[(r) * 68 + (c)]
#define VSS(r, c) Vs[(r) * 72 + (c)]

__global__ __launch_bounds__(128) void attn_tf32(
    const float* __restrict__ qkv, float* __restrict__ out)
{
    extern __shared__ float fsm[];
    float* Qs = fsm;
    float* KP = fsm + 64 * 68;
    float* Vs = fsm + 2 * 64 * 68;

    const int qb = blockIdx.x;
    const int h  = blockIdx.y;
    const int b  = blockIdx.z;
    const int tid  = threadIdx.x;
    const int lane = tid & 31;
    const int wid  = tid >> 5;
    const int g    = lane >> 2;
    const int tg   = lane & 3;
    const int wq   = wid * 16;

#pragma unroll
    for (int i = 0; i < 8; i++) {
        const int idx = tid + i * 128;
        const int row = idx >> 4;
        const int c4  = (idx & 15) << 2;
        *(float4*)&QS(row, c4) =
            *(const float4*)&qkv[((size_t)(b * SEQ + qb * 64 + row)) * (3 * DIM)
                                 + h * HDIM + c4];
    }

    float of[8][4];
    float mi0 = -1e30f, mi1 = -1e30f, li0 = 0.f, li1 = 0.f;
#pragma unroll
    for (int nt = 0; nt < 8; nt++)
#pragma unroll
        for (int r = 0; r < 4; r++) of[nt][r] = 0.f;

    const float scale = 0.03125f;   // 1024^-0.5

    for (int kt = 0; kt < SEQ; kt += 64) {
        __syncthreads();
#pragma unroll
        for (int i = 0; i < 8; i++) {
            const int idx = tid + i * 128;
            const int row = idx >> 4;
            const int c4  = (idx & 15) << 2;
            const size_t base = ((size_t)(b * SEQ + kt + row)) * (3 * DIM) + h * HDIM;
            *(float4*)&KPS(row, c4) = *(const float4*)&qkv[base + DIM + c4];
            *(float4*)&VSS(row, c4) = *(const float4*)&qkv[base + 2 * DIM + c4];
        }
        __syncthreads();

        float sf[8][4];
#pragma unroll
        for (int nt = 0; nt < 8; nt++)
#pragma unroll
            for (int r = 0; r < 4; r++) sf[nt][r] = 0.f;

#pragma unroll
        for (int kk = 0; kk < 64; kk += 8) {
            unsigned a0 = __float_as_uint(QS(wq + g,     kk + tg));
            unsigned a1 = __float_as_uint(QS(wq + g + 8, kk + tg));
            unsigned a2 = __float_as_uint(QS(wq + g,     kk + tg + 4));
            unsigned a3 = __float_as_uint(QS(wq + g + 8, kk + tg + 4));
#pragma unroll
            for (int nt = 0; nt < 8; nt++) {
                unsigned b0 = __float_as_uint(KPS(nt * 8 + g, kk + tg));
                unsigned b1 = __float_as_uint(KPS(nt * 8 + g, kk + tg + 4));
                mma_tf32(sf[nt], a0, a1, a2, a3, b0, b1);
            }
        }

        float m0 = -1e30f, m1 = -1e30f;
#pragma unroll
        for (int nt = 0; nt < 8; nt++) {
            sf[nt][0] *= scale; sf[nt][1] *= scale;
            sf[nt][2] *= scale; sf[nt][3] *= scale;
            m0 = fmaxf(m0, fmaxf(sf[nt][0], sf[nt][1]));
            m1 = fmaxf(m1, fmaxf(sf[nt][2], sf[nt][3]));
        }
        m0 = fmaxf(m0, __shfl_xor_sync(0xffffffffu, m0, 1));
        m0 = fmaxf(m0, __shfl_xor_sync(0xffffffffu, m0, 2));
        m1 = fmaxf(m1, __shfl_xor_sync(0xffffffffu, m1, 1));
        m1 = fmaxf(m1, __shfl_xor_sync(0xffffffffu, m1, 2));

        const float mn0 = fmaxf(mi0, m0);
        const float mn1 = fmaxf(mi1, m1);
        const float corr0 = fast_exp(mi0 - mn0);
        const float corr1 = fast_exp(mi1 - mn1);
        mi0 = mn0; mi1 = mn1;

        float s0 = 0.f, s1 = 0.f;
#pragma unroll
        for (int nt = 0; nt < 8; nt++) {
            sf[nt][0] = fast_exp(sf[nt][0] - mn0);
            sf[nt][1] = fast_exp(sf[nt][1] - mn0);
            sf[nt][2] = fast_exp(sf[nt][2] - mn1);
            sf[nt][3] = fast_exp(sf[nt][3] - mn1);
            s0 += sf[nt][0] + sf[nt][1];
            s1 += sf[nt][2] + sf[nt][3];
        }
        s0 += __shfl_xor_sync(0xffffffffu, s0, 1);
        s0 += __shfl_xor_sync(0xffffffffu, s0, 2);
        s1 += __shfl_xor_sync(0xffffffffu, s1, 1);
        s1 += __shfl_xor_sync(0xffffffffu, s1, 2);

        li0 = li0 * corr0 + s0;
        li1 = li1 * corr1 + s1;
#pragma unroll
        for (int nt = 0; nt < 8; nt++) {
            of[nt][0] *= corr0; of[nt][1] *= corr0;
            of[nt][2] *= corr1; of[nt][3] *= corr1;
        }

        __syncthreads();
#pragma unroll
        for (int nt = 0; nt < 8; nt++) {
            *(float2*)&KPS(wq + g, nt * 8 + 2 * tg) =
                make_float2(to_tf32(sf[nt][0]), to_tf32(sf[nt][1]));
            *(float2*)&KPS(wq + g + 8, nt * 8 + 2 * tg) =
                make_float2(to_tf32(sf[nt][2]), to_tf32(sf[nt][3]));
        }
        __syncthreads();

#pragma unroll
        for (int kk = 0; kk < 64; kk += 8) {
            unsigned a0 = __float_as_uint(KPS(wq + g,     kk + tg));
            unsigned a1 = __float_as_uint(KPS(wq + g + 8, kk + tg));
            unsigned a2 = __float_as_uint(KPS(wq + g,     kk + tg + 4));
            unsigned a3 = __float_as_uint(KPS(wq + g + 8, kk + tg + 4));
#pragma unroll
            for (int nt = 0; nt < 8; nt++) {
                unsigned b0 = __float_as_uint(VSS(kk + tg,     nt * 8 + g));
                unsigned b1 = __float_as_uint(VSS(kk + tg + 4, nt * 8 + g));
                mma_tf32(of[nt], a0, a1, a2, a3, b0, b1);
            }
        }
    }

    const float inv0 = 1.f / li0;
    const float inv1 = 1.f / li1;
    const size_t row0 = (size_t)(b * SEQ + qb * 64 + wq + g);
#pragma unroll
    for (int nt = 0; nt < 8; nt++) {
        const int col = h * HDIM + nt * 8 + 2 * tg;
        *(float2*)&out[row0 * DIM + col] =
            make_float2(to_tf32(of[nt][0] * inv0), to_tf32(of[nt][1] * inv0));
        *(float2*)&out[(row0 + 8) * DIM + col] =
            make_float2(to_tf32(of[nt][2] * inv1), to_tf32(of[nt][3] * inv1));
    }
}

// ---------------------------------------------------------------------------
extern "C" void kernel_launch(void* const* d_in, const int* in_sizes, int n_in,
                              void* d_out, int out_size)
{
    const float* x     = (const float*)d_in[0];
    const float* w_qkv = (const float*)d_in[1];
    const float* w_o   = (const float*)d_in[2];
    const float* b_o   = (const float*)d_in[3];
    float* out = (float*)d_out;

    float *qkv, *att, *xc, *wqkvc, *woc;
    cudaGetSymbolAddress((void**)&qkv, g_qkv);
    cudaGetSymbolAddress((void**)&att, g_att);
    cudaGetSymbolAddress((void**)&xc, g_xc);
    cudaGetSymbolAddress((void**)&wqkvc, g_wqkvc);
    cudaGetSymbolAddress((void**)&woc, g_woc);

    static bool attr_done = false;
    if (!attr_done) {
        cudaFuncSetAttribute(gemm_cp, cudaFuncAttributeMaxDynamicSharedMemorySize,
                             G_SMEM);
        cudaFuncSetAttribute(attn_tf32, cudaFuncAttributeMaxDynamicSharedMemorySize,
                             (2 * 64 * 68 + 64 * 72) * 4);
        attr_done = true;
    }
    const int attn_smem = (2 * 64 * 68 + 64 * 72) * 4;   // 53248 B

    // 0) pre-round inputs to tf32 (GEMMs then run cvt-free on raw data)
    round_tf32<<<(MTOT * DIM / 4 + 255) / 256, 256>>>(x, xc, MTOT * DIM / 4);
    round_tf32<<<(3 * DIM * DIM / 4 + 255) / 256, 256>>>(w_qkv, wqkvc, 3 * DIM * DIM / 4);
    round_tf32<<<(DIM * DIM / 4 + 255) / 256, 256>>>(w_o, woc, DIM * DIM / 4);

    // 1) QKV projection (writes tf32-rounded)
    gemm_cp<<<dim3(3 * DIM / 128, MTOT / 128), 256, G_SMEM>>>(xc, wqkvc, nullptr,
                                                              qkv, 3 * DIM, 1);
    // 2) fused attention (writes tf32-rounded)
    attn_tf32<<<dim3(SEQ / 64, NHEAD, BATCH), 128, attn_smem>>>(qkv, att);
    // 3) output projection + bias (raw fp32 out)
    gemm_cp<<<dim3(DIM / 128, MTOT / 128), 256, G_SMEM>>>(att, woc, b_o, out,
                                                          DIM, 0);
}